// round 1
// baseline (speedup 1.0000x reference)
#include <cuda_runtime.h>
#include <cstdint>

// Problem constants
#define BB   4096
#define NN   8
#define DD   256
#define FFD  2048
#define NDIM 2048          // N*D
#define ROWS 32768         // B*N
#define HALF 2048          // B/2

// Scratch (device globals — no runtime allocation allowed)
__device__ float g_wt[2 * NDIM * NDIM];            // expanded circulant weights, [half][ncol][k]
__device__ float g_xn[BB * NDIM];                  // LN1 output
__device__ float g_x [BB * NDIM];                  // post-TT residual
__device__ float g_yn[BB * NDIM];                  // LN2 output
__device__ float g_hidden[67108864];               // 32768 x 2048 FFN hidden

// ---------------------------------------------------------------------------
// Expand w[d, o, s] (D x D x N) into Wt[jcol = kk*D+o][p = i*D+d] = w[d,o,(kk-i)%8]
// for both halves. NT layout (ncol x K) for the GEMM.
// ---------------------------------------------------------------------------
__global__ void expand_w(const float* __restrict__ w_in, const float* __restrict__ w_out)
{
    int idx = blockIdx.x * blockDim.x + threadIdx.x;     // over NDIM*NDIM
    if (idx >= NDIM * NDIM) return;
    int j = idx >> 11;          // jcol = kk*256 + o
    int p = idx & 2047;         // p    = i*256 + d
    int kk = j >> 8;
    int o  = j & 255;
    int i  = p >> 8;
    int d  = p & 255;
    int s  = (kk - i + 8) & 7;
    int widx = (d * DD + o) * NN + s;
    g_wt[idx]               = w_in [widx];
    g_wt[NDIM * NDIM + idx] = w_out[widx];
}

// ---------------------------------------------------------------------------
// LayerNorm over D=256. One warp per row, 8 rows per 256-thread block.
// PH=0: in = ent (param), out = g_xn.  PH=1: in = g_x, out = g_yn.
// ---------------------------------------------------------------------------
template<int PH>
__global__ __launch_bounds__(256) void ln_kernel(const float* __restrict__ xin_ext,
                                                 const float* __restrict__ gamma,
                                                 const float* __restrict__ beta)
{
    const float* x   = (PH == 0) ? xin_ext : g_x;
    float*       out = (PH == 0) ? g_xn    : g_yn;

    int warp = threadIdx.x >> 5;
    int lane = threadIdx.x & 31;
    int row  = blockIdx.x * 8 + warp;

    const float* xr = x + (size_t)row * DD;
    float v[8];
    float sum = 0.f;
#pragma unroll
    for (int i = 0; i < 8; i++) { v[i] = xr[lane + 32 * i]; sum += v[i]; }
#pragma unroll
    for (int off = 16; off; off >>= 1) sum += __shfl_xor_sync(0xffffffffu, sum, off);
    float mu = sum * (1.f / 256.f);

    float var = 0.f;
#pragma unroll
    for (int i = 0; i < 8; i++) { float t = v[i] - mu; var += t * t; }
#pragma unroll
    for (int off = 16; off; off >>= 1) var += __shfl_xor_sync(0xffffffffu, var, off);
    float rstd = rsqrtf(var * (1.f / 256.f) + 1e-5f);

    float* orow = out + (size_t)row * DD;
#pragma unroll
    for (int i = 0; i < 8; i++) {
        int c = lane + 32 * i;
        orow[c] = (v[i] - mu) * rstd * gamma[c] + beta[c];
    }
}

// ---------------------------------------------------------------------------
// Tiled NT SGEMM: C[m, n] = epilogue( sum_k A[m,k] * Bt[n,k] )
// 128x128 block tile, BK=16, 256 threads, 8x8 microtile per thread.
// MODE 0: TT product.  A=g_xn (K=2048), Bt=g_wt (per-half), res=ent, C=g_x.
// MODE 1: FFN-1.       A=g_yn (K=256),  Bt=W1, +bias1, ReLU, C=g_hidden.
// MODE 2: FFN-2.       A=g_hidden (K=2048), Bt=W2, +bias2 + g_x, C=out.
// All dims divide tile sizes evenly — no bounds checks.
// ---------------------------------------------------------------------------
template<int MODE>
__global__ __launch_bounds__(256) void gemm_nt(const float* __restrict__ Bt_ext,
                                               const float* __restrict__ bias,
                                               const float* __restrict__ res_ext,
                                               float* __restrict__ C_ext)
{
    constexpr int Ncol = (MODE == 2) ? 256 : 2048;
    constexpr int K    = (MODE == 1) ? 256 : 2048;
    constexpr int BM = 128, BN = 128, BK = 16;

    const float* A;
    const float* Bt;
    const float* res;
    float* C;
    if constexpr (MODE == 0) {
        A   = g_xn;
        Bt  = (blockIdx.y * BM < HALF) ? g_wt : (g_wt + NDIM * NDIM);
        res = res_ext;                 // ent_seq, flattened (4096 x 2048)
        C   = g_x;
    } else if constexpr (MODE == 1) {
        A   = g_yn;                    // (32768 x 256)
        Bt  = Bt_ext;                  // W1 (2048 x 256)
        res = nullptr;
        C   = g_hidden;
    } else {
        A   = g_hidden;                // (32768 x 2048)
        Bt  = Bt_ext;                  // W2 (256 x 2048)
        res = g_x;                     // viewed as (32768 x 256)
        C   = C_ext;                   // d_out
    }

    __shared__ float As[BK][BM];
    __shared__ float Bs[BK][BN];

    int tid = threadIdx.x;
    int tx  = tid & 15;
    int ty  = tid >> 4;
    int bm  = blockIdx.y * BM;
    int bn  = blockIdx.x * BN;

    int lr = tid >> 2;            // 0..63
    int lc = (tid & 3) << 2;      // 0,4,8,12

    float acc[8][8];
#pragma unroll
    for (int i = 0; i < 8; i++)
#pragma unroll
        for (int j = 0; j < 8; j++) acc[i][j] = 0.f;

    for (int k0 = 0; k0 < K; k0 += BK) {
#pragma unroll
        for (int h = 0; h < 2; h++) {
            int row = lr + h * 64;
            float4 v = *(const float4*)&A[(size_t)(bm + row) * K + k0 + lc];
            As[lc + 0][row] = v.x; As[lc + 1][row] = v.y;
            As[lc + 2][row] = v.z; As[lc + 3][row] = v.w;
        }
#pragma unroll
        for (int h = 0; h < 2; h++) {
            int row = lr + h * 64;
            float4 v = *(const float4*)&Bt[(size_t)(bn + row) * K + k0 + lc];
            Bs[lc + 0][row] = v.x; Bs[lc + 1][row] = v.y;
            Bs[lc + 2][row] = v.z; Bs[lc + 3][row] = v.w;
        }
        __syncthreads();

#pragma unroll
        for (int kk = 0; kk < BK; kk++) {
            float4 a0 = *(const float4*)&As[kk][ty * 8];
            float4 a1 = *(const float4*)&As[kk][ty * 8 + 4];
            float4 b0 = *(const float4*)&Bs[kk][tx * 8];
            float4 b1 = *(const float4*)&Bs[kk][tx * 8 + 4];
            float am[8] = {a0.x, a0.y, a0.z, a0.w, a1.x, a1.y, a1.z, a1.w};
            float bv[8] = {b0.x, b0.y, b0.z, b0.w, b1.x, b1.y, b1.z, b1.w};
#pragma unroll
            for (int i = 0; i < 8; i++)
#pragma unroll
                for (int j = 0; j < 8; j++)
                    acc[i][j] += am[i] * bv[j];
        }
        __syncthreads();
    }

#pragma unroll
    for (int i = 0; i < 8; i++) {
        int gm = bm + ty * 8 + i;
#pragma unroll
        for (int j = 0; j < 8; j++) {
            int gn = bn + tx * 8 + j;
            float v = acc[i][j];
            if constexpr (MODE == 0) {
                v += res[(size_t)gm * Ncol + gn];
            } else if constexpr (MODE == 1) {
                v += bias[gn];
                v = fmaxf(v, 0.f);
            } else {
                v += bias[gn] + res[(size_t)gm * Ncol + gn];
            }
            C[(size_t)gm * Ncol + gn] = v;
        }
    }
}

// ---------------------------------------------------------------------------
extern "C" void kernel_launch(void* const* d_in, const int* in_sizes, int n_in,
                              void* d_out, int out_size)
{
    const float* ent    = (const float*)d_in[0];
    const float* w_in   = (const float*)d_in[1];
    const float* w_out  = (const float*)d_in[2];
    const float* W1     = (const float*)d_in[3];
    const float* bias1  = (const float*)d_in[4];
    const float* W2     = (const float*)d_in[5];
    const float* bias2  = (const float*)d_in[6];
    const float* gamma1 = (const float*)d_in[7];
    const float* beta1  = (const float*)d_in[8];
    const float* gamma2 = (const float*)d_in[9];
    const float* beta2  = (const float*)d_in[10];
    float* out = (float*)d_out;

    // 1. expand circulant weights into two 2048x2048 NT matrices
    expand_w<<<(NDIM * NDIM + 255) / 256, 256>>>(w_in, w_out);

    // 2. LN1: ent (32768 x 256) -> g_xn
    ln_kernel<0><<<ROWS / 8, 256>>>(ent, gamma1, beta1);

    // 3. TT GEMM + residual: g_x = ent + g_xn @ Wbig^T   (4096 x 2048)
    gemm_nt<0><<<dim3(NDIM / 128, BB / 128), 256>>>(nullptr, nullptr, ent, nullptr);

    // 4. LN2: g_x -> g_yn
    ln_kernel<1><<<ROWS / 8, 256>>>(nullptr, gamma2, beta2);

    // 5. FFN GEMM1 + bias + ReLU: g_hidden = relu(g_yn @ W1^T + b1)  (32768 x 2048)
    gemm_nt<1><<<dim3(FFD / 128, ROWS / 128), 256>>>(W1, bias1, nullptr, nullptr);

    // 6. FFN GEMM2 + bias + residual: out = g_x + g_hidden @ W2^T + b2  (32768 x 256)
    gemm_nt<2><<<dim3(DD / 128, ROWS / 128), 256>>>(W2, bias2, nullptr, out);
}

// round 3
// speedup vs baseline: 2.3242x; 2.3242x over previous
#include <cuda_runtime.h>
#include <cstdint>

// ---------------------------------------------------------------------------
// Problem constants
// ---------------------------------------------------------------------------
#define BB   4096
#define NN   8
#define DD   256
#define FFD  2048
#define NDIM 2048          // N*D
#define ROWS 32768         // B*N

// ---------------------------------------------------------------------------
// Scratch (device globals — no runtime allocation allowed)
// ---------------------------------------------------------------------------
__device__ float g_wt[2u * NDIM * NDIM];        // expanded circulant weights (2 halves stacked: 4096 x 2048)
__device__ float g_xn[(size_t)BB * NDIM];       // LN1 out (tf32-rounded)
__device__ float g_x [(size_t)BB * NDIM];       // post-TT residual (full fp32)
__device__ float g_yn[(size_t)BB * NDIM];       // LN2 out (tf32-rounded)
__device__ float g_hidden[(size_t)ROWS * FFD];  // FFN hidden (tf32-rounded)
__device__ float g_w1r[FFD * DD];               // W1 tf32-rounded
__device__ float g_w2r[DD * FFD];               // W2 tf32-rounded

// ---------------------------------------------------------------------------
// Helpers
// ---------------------------------------------------------------------------
__device__ __forceinline__ float to_tf32(float x) {
    float r;
    asm("cvt.rna.tf32.f32 %0, %1;" : "=f"(r) : "f"(x));
    return r;
}

__device__ __forceinline__ uint32_t smem_u32(const void* p) {
    uint32_t a;
    asm("{ .reg .u64 t; cvta.to.shared.u64 t, %1; cvt.u32.u64 %0, t; }"
        : "=r"(a) : "l"(p));
    return a;
}

#define CP_ASYNC16(dst_u32, src_ptr) \
    asm volatile("cp.async.cg.shared.global [%0], [%1], 16;" \
                 :: "r"(dst_u32), "l"(src_ptr) : "memory")
#define CP_COMMIT() asm volatile("cp.async.commit_group;" ::: "memory")
#define CP_WAIT1()  asm volatile("cp.async.wait_group 1;" ::: "memory")
#define CP_WAIT0()  asm volatile("cp.async.wait_group 0;" ::: "memory")

__device__ __forceinline__ void mma_tf32(float& c0, float& c1, float& c2, float& c3,
                                         uint32_t a0, uint32_t a1, uint32_t a2, uint32_t a3,
                                         uint32_t b0, uint32_t b1) {
    asm volatile(
        "mma.sync.aligned.m16n8k8.row.col.f32.tf32.tf32.f32 "
        "{%0,%1,%2,%3}, {%4,%5,%6,%7}, {%8,%9}, {%0,%1,%2,%3};"
        : "+f"(c0), "+f"(c1), "+f"(c2), "+f"(c3)
        : "r"(a0), "r"(a1), "r"(a2), "r"(a3), "r"(b0), "r"(b1));
}

// ---------------------------------------------------------------------------
// Weight expansion + rounding
// Wt[jcol = kk*D+o][p = i*D+d] = w[d,o,(kk-i)%8]
// ---------------------------------------------------------------------------
__global__ void expand_w(const float* __restrict__ w_in, const float* __restrict__ w_out)
{
    int idx = blockIdx.x * blockDim.x + threadIdx.x;
    if (idx >= NDIM * NDIM) return;
    int j = idx >> 11;
    int p = idx & 2047;
    int kk = j >> 8, o = j & 255;
    int i  = p >> 8, d = p & 255;
    int s  = (kk - i + 8) & 7;
    int widx = (d * DD + o) * NN + s;
    g_wt[idx]               = to_tf32(w_in [widx]);
    g_wt[NDIM * NDIM + idx] = to_tf32(w_out[widx]);
}

__global__ void round_w(const float* __restrict__ W1, const float* __restrict__ W2)
{
    int idx = blockIdx.x * blockDim.x + threadIdx.x;
    g_w1r[idx] = to_tf32(W1[idx]);
    g_w2r[idx] = to_tf32(W2[idx]);
}

// ---------------------------------------------------------------------------
// LayerNorm over D=256, one warp per row; output tf32-rounded
// ---------------------------------------------------------------------------
template<int PH>
__global__ __launch_bounds__(256) void ln_kernel(const float* __restrict__ xin_ext,
                                                 const float* __restrict__ gamma,
                                                 const float* __restrict__ beta)
{
    const float* x   = (PH == 0) ? xin_ext : g_x;
    float*       out = (PH == 0) ? g_xn    : g_yn;

    int warp = threadIdx.x >> 5;
    int lane = threadIdx.x & 31;
    int row  = blockIdx.x * 8 + warp;

    const float* xr = x + (size_t)row * DD;
    float v[8];
    float sum = 0.f;
#pragma unroll
    for (int i = 0; i < 8; i++) { v[i] = xr[lane + 32 * i]; sum += v[i]; }
#pragma unroll
    for (int off = 16; off; off >>= 1) sum += __shfl_xor_sync(0xffffffffu, sum, off);
    float mu = sum * (1.f / 256.f);

    float var = 0.f;
#pragma unroll
    for (int i = 0; i < 8; i++) { float t = v[i] - mu; var += t * t; }
#pragma unroll
    for (int off = 16; off; off >>= 1) var += __shfl_xor_sync(0xffffffffu, var, off);
    float rstd = rsqrtf(var * (1.f / 256.f) + 1e-5f);

    float* orow = out + (size_t)row * DD;
#pragma unroll
    for (int i = 0; i < 8; i++) {
        int c = lane + 32 * i;
        orow[c] = to_tf32((v[i] - mu) * rstd * gamma[c] + beta[c]);
    }
}

// ---------------------------------------------------------------------------
// tf32 mma.sync GEMM: C[m,n] = epi( sum_k A[m,k] * Bt[n,k] )
// BM=128 BN=128 BK=32, 256 threads = 2(M) x 4(N) warps, warp tile 64x32,
// m16n8k8 atoms (4x4 per warp), double-buffered cp.async.
//
// MODE 0: TT (A=g_xn K=2048, Bt=g_wt rows [bn + halfsel*2048], +res(ent) -> g_x)
// MODE 1: FFN1 (A=g_yn K=256, Bt=g_w1r, relu(+bias1), tf32-round -> g_hidden)
// MODE 2: FFN2 (A=g_hidden K=2048, Bt=g_w2r, +bias2 +g_x -> out)
// ---------------------------------------------------------------------------
#define BM 128
#define BN 128
#define BK 32
#define PITCH 36                       // floats per smem row (32 + 4 pad)
#define TILE_FLOATS (128 * PITCH)      // one matrix, one stage
#define STAGE_FLOATS (2 * TILE_FLOATS) // A + B
#define GEMM_SMEM (2 * STAGE_FLOATS * 4)

template<int MODE>
__global__ __launch_bounds__(256, 1) void gemm_mma(
    const float* __restrict__ bias,
    const float* __restrict__ res,
    float* __restrict__ C)
{
    constexpr int K    = (MODE == 1) ? 256 : 2048;
    constexpr int Ncol = (MODE == 2) ? 256 : 2048;
    constexpr int KT   = K / BK;

    const float* A;
    const float* Bt;
    if constexpr (MODE == 0)      { A = g_xn;     Bt = g_wt;  }
    else if constexpr (MODE == 1) { A = g_yn;     Bt = g_w1r; }
    else                          { A = g_hidden; Bt = g_w2r; }

    extern __shared__ float sm[];
    // stage s: A at s*STAGE_FLOATS, B at s*STAGE_FLOATS + TILE_FLOATS

    int tid  = threadIdx.x;
    int wid  = tid >> 5;
    int lane = tid & 31;
    int g    = lane >> 2;      // groupID
    int tg   = lane & 3;       // thread-in-group
    int wm   = wid & 1;        // warp M index (0..1)
    int wn   = wid >> 1;       // warp N index (0..3)

    int bm = blockIdx.y * BM;
    int bn = blockIdx.x * BN;
    int brow = bn;
    if (MODE == 0 && bm >= 2048) brow += 2048;   // second-half weight block

    // cp.async assignment: thread t covers row = t>>1, 4 x 16B segs
    int ldrow = tid >> 1;
    int ldseg = (tid & 1) * 4;

    const char* Abase = (const char*)(A  + (size_t)(bm   + ldrow) * K) + ldseg * 16;
    const char* Bbase = (const char*)(Bt + (size_t)(brow + ldrow) * K) + ldseg * 16;
    uint32_t sA = smem_u32(sm) + (uint32_t)(ldrow * PITCH * 4 + ldseg * 16);
    uint32_t sB = sA + TILE_FLOATS * 4;

    auto prefetch = [&](int kt, int st) {
        uint32_t off = (uint32_t)(st * STAGE_FLOATS * 4);
        const char* ag = Abase + (size_t)kt * BK * 4;
        const char* bg = Bbase + (size_t)kt * BK * 4;
#pragma unroll
        for (int s = 0; s < 4; s++) {
            CP_ASYNC16(sA + off + s * 16, ag + s * 16);
            CP_ASYNC16(sB + off + s * 16, bg + s * 16);
        }
    };

    float acc[4][4][4];
#pragma unroll
    for (int mi = 0; mi < 4; mi++)
#pragma unroll
        for (int ni = 0; ni < 4; ni++)
#pragma unroll
            for (int c = 0; c < 4; c++) acc[mi][ni][c] = 0.f;

    prefetch(0, 0);
    CP_COMMIT();

    for (int kt = 0; kt < KT; kt++) {
        if (kt + 1 < KT) {
            prefetch(kt + 1, (kt + 1) & 1);
            CP_COMMIT();
            CP_WAIT1();
        } else {
            CP_WAIT0();
        }
        __syncthreads();

        const float* As = sm + (kt & 1) * STAGE_FLOATS;
        const float* Bs = As + TILE_FLOATS;
        const uint32_t* Asu = (const uint32_t*)As;
        const uint32_t* Bsu = (const uint32_t*)Bs;

#pragma unroll
        for (int ka = 0; ka < 4; ka++) {
            uint32_t af[4][4];
#pragma unroll
            for (int mi = 0; mi < 4; mi++) {
                int m0 = wm * 64 + mi * 16;
                int kc = ka * 8 + tg;
                af[mi][0] = Asu[(m0 + g)     * PITCH + kc];
                af[mi][1] = Asu[(m0 + g + 8) * PITCH + kc];
                af[mi][2] = Asu[(m0 + g)     * PITCH + kc + 4];
                af[mi][3] = Asu[(m0 + g + 8) * PITCH + kc + 4];
            }
            uint32_t bf[4][2];
#pragma unroll
            for (int ni = 0; ni < 4; ni++) {
                int n0 = wn * 32 + ni * 8;
                int kc = ka * 8 + tg;
                bf[ni][0] = Bsu[(n0 + g) * PITCH + kc];
                bf[ni][1] = Bsu[(n0 + g) * PITCH + kc + 4];
            }
#pragma unroll
            for (int mi = 0; mi < 4; mi++)
#pragma unroll
                for (int ni = 0; ni < 4; ni++)
                    mma_tf32(acc[mi][ni][0], acc[mi][ni][1], acc[mi][ni][2], acc[mi][ni][3],
                             af[mi][0], af[mi][1], af[mi][2], af[mi][3],
                             bf[ni][0], bf[ni][1]);
        }
        __syncthreads();
    }

    // ---- epilogue ----
#pragma unroll
    for (int mi = 0; mi < 4; mi++) {
#pragma unroll
        for (int half = 0; half < 2; half++) {
            int row = bm + wm * 64 + mi * 16 + g + half * 8;
#pragma unroll
            for (int ni = 0; ni < 4; ni++) {
                int col = bn + wn * 32 + ni * 8 + tg * 2;
                float v0 = acc[mi][ni][half * 2 + 0];
                float v1 = acc[mi][ni][half * 2 + 1];
                if constexpr (MODE == 0) {
                    const float2 rv = *(const float2*)&res[(size_t)row * 2048 + col];
                    v0 += rv.x; v1 += rv.y;
                } else if constexpr (MODE == 1) {
                    v0 = to_tf32(fmaxf(v0 + bias[col],     0.f));
                    v1 = to_tf32(fmaxf(v1 + bias[col + 1], 0.f));
                } else {
                    const float2 rv = *(const float2*)&res[(size_t)row * 256 + col];
                    v0 += bias[col]     + rv.x;
                    v1 += bias[col + 1] + rv.y;
                }
                float2 o; o.x = v0; o.y = v1;
                *(float2*)&C[(size_t)row * Ncol + col] = o;
            }
        }
    }
}

// ---------------------------------------------------------------------------
// Host side
// ---------------------------------------------------------------------------
extern "C" void kernel_launch(void* const* d_in, const int* in_sizes, int n_in,
                              void* d_out, int out_size)
{
    const float* ent    = (const float*)d_in[0];
    const float* w_in   = (const float*)d_in[1];
    const float* w_out  = (const float*)d_in[2];
    const float* W1     = (const float*)d_in[3];
    const float* bias1  = (const float*)d_in[4];
    const float* W2     = (const float*)d_in[5];
    const float* bias2  = (const float*)d_in[6];
    const float* gamma1 = (const float*)d_in[7];
    const float* beta1  = (const float*)d_in[8];
    const float* gamma2 = (const float*)d_in[9];
    const float* beta2  = (const float*)d_in[10];
    float* out = (float*)d_out;

    void* p_x;
    void* p_hid;
    cudaGetSymbolAddress(&p_x,   g_x);
    cudaGetSymbolAddress(&p_hid, g_hidden);

    static bool attr_done = false;
    if (!attr_done) {
        cudaFuncSetAttribute(gemm_mma<0>, cudaFuncAttributeMaxDynamicSharedMemorySize, GEMM_SMEM);
        cudaFuncSetAttribute(gemm_mma<1>, cudaFuncAttributeMaxDynamicSharedMemorySize, GEMM_SMEM);
        cudaFuncSetAttribute(gemm_mma<2>, cudaFuncAttributeMaxDynamicSharedMemorySize, GEMM_SMEM);
        attr_done = true;
    }

    // 1. expand circulant weights + round W1/W2 to tf32
    expand_w<<<(NDIM * NDIM + 255) / 256, 256>>>(w_in, w_out);
    round_w<<<(FFD * DD) / 256, 256>>>(W1, W2);

    // 2. LN1: ent -> g_xn (tf32)
    ln_kernel<0><<<ROWS / 8, 256>>>(ent, gamma1, beta1);

    // 3. TT GEMM + residual: g_x = ent + g_xn @ Wbig^T  (4096 x 2048)
    gemm_mma<0><<<dim3(2048 / BN, 4096 / BM), 256, GEMM_SMEM>>>(nullptr, ent, (float*)p_x);

    // 4. LN2: g_x -> g_yn (tf32)
    ln_kernel<1><<<ROWS / 8, 256>>>(nullptr, gamma2, beta2);

    // 5. FFN1: g_hidden = tf32(relu(g_yn @ W1^T + b1))  (32768 x 2048)
    gemm_mma<1><<<dim3(2048 / BN, 32768 / BM), 256, GEMM_SMEM>>>(bias1, nullptr, (float*)p_hid);

    // 6. FFN2: out = g_x + g_hidden @ W2^T + b2  (32768 x 256)
    gemm_mma<2><<<dim3(256 / BN, 32768 / BM), 256, GEMM_SMEM>>>(bias2, (const float*)p_x, out);
}

// round 5
// speedup vs baseline: 2.5827x; 1.1112x over previous
#include <cuda_runtime.h>
#include <cstdint>

// ---------------------------------------------------------------------------
// Problem constants
// ---------------------------------------------------------------------------
#define BB   4096
#define NN   8
#define DD   256
#define FFD  2048
#define NDIM 2048          // N*D
#define ROWS 32768         // B*N

// ---------------------------------------------------------------------------
// Scratch (device globals — no runtime allocation allowed)
// ---------------------------------------------------------------------------
__device__ float g_wt[2u * NDIM * NDIM];        // expanded circulant weights (2 halves stacked: 4096 x 2048)
__device__ float g_xn[(size_t)BB * NDIM];       // LN1 out (tf32-rounded)
__device__ float g_x [(size_t)BB * NDIM];       // post-TT residual (full fp32)
__device__ float g_yn[(size_t)BB * NDIM];       // LN2 out (tf32-rounded)
__device__ float g_hidden[(size_t)ROWS * FFD];  // FFN hidden (tf32-rounded)
__device__ float g_w1r[FFD * DD];               // W1 tf32-rounded
__device__ float g_w2r[DD * FFD];               // W2 tf32-rounded

// ---------------------------------------------------------------------------
// Helpers
// ---------------------------------------------------------------------------
__device__ __forceinline__ float to_tf32(float x) {
    float r;
    asm("cvt.rna.tf32.f32 %0, %1;" : "=f"(r) : "f"(x));
    return r;
}

__device__ __forceinline__ uint32_t smem_u32(const void* p) {
    uint32_t a;
    asm("{ .reg .u64 t; cvta.to.shared.u64 t, %1; cvt.u32.u64 %0, t; }"
        : "=r"(a) : "l"(p));
    return a;
}

#define CP_ASYNC16(dst_u32, src_ptr) \
    asm volatile("cp.async.cg.shared.global [%0], [%1], 16;" \
                 :: "r"(dst_u32), "l"(src_ptr) : "memory")
#define CP_COMMIT() asm volatile("cp.async.commit_group;" ::: "memory")
#define CP_WAIT0()  asm volatile("cp.async.wait_group 0;" ::: "memory")

__device__ __forceinline__ void mma_tf32(float& c0, float& c1, float& c2, float& c3,
                                         uint32_t a0, uint32_t a1, uint32_t a2, uint32_t a3,
                                         uint32_t b0, uint32_t b1) {
    asm volatile(
        "mma.sync.aligned.m16n8k8.row.col.f32.tf32.tf32.f32 "
        "{%0,%1,%2,%3}, {%4,%5,%6,%7}, {%8,%9}, {%0,%1,%2,%3};"
        : "+f"(c0), "+f"(c1), "+f"(c2), "+f"(c3)
        : "r"(a0), "r"(a1), "r"(a2), "r"(a3), "r"(b0), "r"(b1));
}

// ---------------------------------------------------------------------------
// Weight expansion + rounding
// Wt[jcol = kk*D+o][p = i*D+d] = w[d,o,(kk-i)%8]
// ---------------------------------------------------------------------------
__global__ void expand_w(const float* __restrict__ w_in, const float* __restrict__ w_out)
{
    int idx = blockIdx.x * blockDim.x + threadIdx.x;
    if (idx >= NDIM * NDIM) return;
    int j = idx >> 11;
    int p = idx & 2047;
    int kk = j >> 8, o = j & 255;
    int i  = p >> 8, d = p & 255;
    int s  = (kk - i + 8) & 7;
    int widx = (d * DD + o) * NN + s;
    g_wt[idx]               = to_tf32(w_in [widx]);
    g_wt[NDIM * NDIM + idx] = to_tf32(w_out[widx]);
}

__global__ void round_w(const float* __restrict__ W1, const float* __restrict__ W2)
{
    int idx = blockIdx.x * blockDim.x + threadIdx.x;
    g_w1r[idx] = to_tf32(W1[idx]);
    g_w2r[idx] = to_tf32(W2[idx]);
}

// ---------------------------------------------------------------------------
// LayerNorm over D=256, one warp per row; output tf32-rounded
// ---------------------------------------------------------------------------
template<int PH>
__global__ __launch_bounds__(256) void ln_kernel(const float* __restrict__ xin_ext,
                                                 const float* __restrict__ gamma,
                                                 const float* __restrict__ beta)
{
    const float* x   = (PH == 0) ? xin_ext : g_x;
    float*       out = (PH == 0) ? g_xn    : g_yn;

    int warp = threadIdx.x >> 5;
    int lane = threadIdx.x & 31;
    int row  = blockIdx.x * 8 + warp;

    const float* xr = x + (size_t)row * DD;
    float v[8];
    float sum = 0.f;
#pragma unroll
    for (int i = 0; i < 8; i++) { v[i] = xr[lane + 32 * i]; sum += v[i]; }
#pragma unroll
    for (int off = 16; off; off >>= 1) sum += __shfl_xor_sync(0xffffffffu, sum, off);
    float mu = sum * (1.f / 256.f);

    float var = 0.f;
#pragma unroll
    for (int i = 0; i < 8; i++) { float t = v[i] - mu; var += t * t; }
#pragma unroll
    for (int off = 16; off; off >>= 1) var += __shfl_xor_sync(0xffffffffu, var, off);
    float rstd = rsqrtf(var * (1.f / 256.f) + 1e-5f);

    float* orow = out + (size_t)row * DD;
#pragma unroll
    for (int i = 0; i < 8; i++) {
        int c = lane + 32 * i;
        orow[c] = to_tf32((v[i] - mu) * rstd * gamma[c] + beta[c]);
    }
}

// ---------------------------------------------------------------------------
// tf32 mma.sync GEMM: C[m,n] = epi( sum_k A[m,k] * Bt[n,k] )
// BM=128 BN=128 BK=32, 256 threads = 2(M) x 4(N) warps, warp tile 64x32,
// m16n8k8 atoms (4x4 per warp), double-buffered cp.async,
// ONE __syncthreads per K-tile, 2 CTAs/SM (128-reg cap).
//
// MODE 0: TT (A=g_xn K=2048, Bt=g_wt rows [bn + halfsel*2048], +res(ent) -> g_x)
// MODE 1: FFN1 (A=g_yn K=256, Bt=g_w1r, relu(+bias1), tf32-round -> g_hidden)
// MODE 2: FFN2 (A=g_hidden K=2048, Bt=g_w2r, +bias2 +g_x -> out)
// ---------------------------------------------------------------------------
#define BM 128
#define BN 128
#define BK 32
#define PITCH 36                       // floats per smem row (32 + 4 pad)
#define TILE_FLOATS (128 * PITCH)      // one matrix, one stage
#define STAGE_FLOATS (2 * TILE_FLOATS) // A + B
#define GEMM_SMEM (2 * STAGE_FLOATS * 4)

template<int MODE>
__global__ __launch_bounds__(256, 2) void gemm_mma(
    const float* __restrict__ bias,
    const float* __restrict__ res,
    float* __restrict__ C)
{
    constexpr int K    = (MODE == 1) ? 256 : 2048;
    constexpr int Ncol = (MODE == 2) ? 256 : 2048;
    constexpr int KT   = K / BK;

    const float* A;
    const float* Bt;
    if constexpr (MODE == 0)      { A = g_xn;     Bt = g_wt;  }
    else if constexpr (MODE == 1) { A = g_yn;     Bt = g_w1r; }
    else                          { A = g_hidden; Bt = g_w2r; }

    extern __shared__ float sm[];

    int tid  = threadIdx.x;
    int wid  = tid >> 5;
    int lane = tid & 31;
    int g    = lane >> 2;      // groupID
    int tg   = lane & 3;       // thread-in-group
    int wm   = wid & 1;        // warp M index (0..1)
    int wn   = wid >> 1;       // warp N index (0..3)

    int bm = blockIdx.y * BM;
    int bn = blockIdx.x * BN;
    int brow = bn;
    if (MODE == 0 && bm >= 2048) brow += 2048;   // second-half weight block

    // cp.async assignment: thread t covers row = t>>1, 4 x 16B segs
    int ldrow = tid >> 1;
    int ldseg = (tid & 1) * 4;

    const char* Abase = (const char*)(A  + (size_t)(bm   + ldrow) * K) + ldseg * 16;
    const char* Bbase = (const char*)(Bt + (size_t)(brow + ldrow) * K) + ldseg * 16;
    uint32_t sA = smem_u32(sm) + (uint32_t)(ldrow * PITCH * 4 + ldseg * 16);
    uint32_t sB = sA + TILE_FLOATS * 4;

    auto prefetch = [&](int kt, int st) {
        uint32_t off = (uint32_t)(st * STAGE_FLOATS * 4);
        const char* ag = Abase + (size_t)kt * BK * 4;
        const char* bg = Bbase + (size_t)kt * BK * 4;
#pragma unroll
        for (int s = 0; s < 4; s++) {
            CP_ASYNC16(sA + off + s * 16, ag + s * 16);
            CP_ASYNC16(sB + off + s * 16, bg + s * 16);
        }
    };

    float acc[4][4][4];
#pragma unroll
    for (int mi = 0; mi < 4; mi++)
#pragma unroll
        for (int ni = 0; ni < 4; ni++)
#pragma unroll
            for (int c = 0; c < 4; c++) acc[mi][ni][c] = 0.f;

    prefetch(0, 0);
    CP_COMMIT();

    for (int kt = 0; kt < KT; kt++) {
        // All committed groups (through kt) complete for this thread...
        CP_WAIT0();
        // ...and for everyone; also: every warp finished compute(kt-1), so
        // stage (kt+1)&1 is safe to overwrite after this barrier.
        __syncthreads();

        // Overlap next tile's loads with this tile's MMAs.
        if (kt + 1 < KT) {
            prefetch(kt + 1, (kt + 1) & 1);
            CP_COMMIT();
        }

        const float* As = sm + (kt & 1) * STAGE_FLOATS;
        const float* Bs = As + TILE_FLOATS;
        const uint32_t* Asu = (const uint32_t*)As;
        const uint32_t* Bsu = (const uint32_t*)Bs;

#pragma unroll
        for (int ka = 0; ka < 4; ka++) {
            int kc = ka * 8 + tg;
            uint32_t bf[4][2];
#pragma unroll
            for (int ni = 0; ni < 4; ni++) {
                int n0 = wn * 32 + ni * 8;
                bf[ni][0] = Bsu[(n0 + g) * PITCH + kc];
                bf[ni][1] = Bsu[(n0 + g) * PITCH + kc + 4];
            }
#pragma unroll
            for (int mi = 0; mi < 4; mi++) {
                int m0 = wm * 64 + mi * 16;
                uint32_t a0 = Asu[(m0 + g)     * PITCH + kc];
                uint32_t a1 = Asu[(m0 + g + 8) * PITCH + kc];
                uint32_t a2 = Asu[(m0 + g)     * PITCH + kc + 4];
                uint32_t a3 = Asu[(m0 + g + 8) * PITCH + kc + 4];
#pragma unroll
                for (int ni = 0; ni < 4; ni++)
                    mma_tf32(acc[mi][ni][0], acc[mi][ni][1], acc[mi][ni][2], acc[mi][ni][3],
                             a0, a1, a2, a3, bf[ni][0], bf[ni][1]);
            }
        }
    }

    // ---- epilogue ----
#pragma unroll
    for (int mi = 0; mi < 4; mi++) {
#pragma unroll
        for (int half = 0; half < 2; half++) {
            int row = bm + wm * 64 + mi * 16 + g + half * 8;
#pragma unroll
            for (int ni = 0; ni < 4; ni++) {
                int col = bn + wn * 32 + ni * 8 + tg * 2;
                float v0 = acc[mi][ni][half * 2 + 0];
                float v1 = acc[mi][ni][half * 2 + 1];
                if constexpr (MODE == 0) {
                    const float2 rv = *(const float2*)&res[(size_t)row * 2048 + col];
                    v0 += rv.x; v1 += rv.y;
                } else if constexpr (MODE == 1) {
                    v0 = to_tf32(fmaxf(v0 + bias[col],     0.f));
                    v1 = to_tf32(fmaxf(v1 + bias[col + 1], 0.f));
                } else {
                    const float2 rv = *(const float2*)&res[(size_t)row * 256 + col];
                    v0 += bias[col]     + rv.x;
                    v1 += bias[col + 1] + rv.y;
                }
                float2 o; o.x = v0; o.y = v1;
                *(float2*)&C[(size_t)row * Ncol + col] = o;
            }
        }
    }
}

// ---------------------------------------------------------------------------
// Host side
// ---------------------------------------------------------------------------
extern "C" void kernel_launch(void* const* d_in, const int* in_sizes, int n_in,
                              void* d_out, int out_size)
{
    const float* ent    = (const float*)d_in[0];
    const float* w_in   = (const float*)d_in[1];
    const float* w_out  = (const float*)d_in[2];
    const float* W1     = (const float*)d_in[3];
    const float* bias1  = (const float*)d_in[4];
    const float* W2     = (const float*)d_in[5];
    const float* bias2  = (const float*)d_in[6];
    const float* gamma1 = (const float*)d_in[7];
    const float* beta1  = (const float*)d_in[8];
    const float* gamma2 = (const float*)d_in[9];
    const float* beta2  = (const float*)d_in[10];
    float* out = (float*)d_out;

    void* p_x;
    void* p_hid;
    cudaGetSymbolAddress(&p_x,   g_x);
    cudaGetSymbolAddress(&p_hid, g_hidden);

    static bool attr_done = false;
    if (!attr_done) {
        cudaFuncSetAttribute(gemm_mma<0>, cudaFuncAttributeMaxDynamicSharedMemorySize, GEMM_SMEM);
        cudaFuncSetAttribute(gemm_mma<1>, cudaFuncAttributeMaxDynamicSharedMemorySize, GEMM_SMEM);
        cudaFuncSetAttribute(gemm_mma<2>, cudaFuncAttributeMaxDynamicSharedMemorySize, GEMM_SMEM);
        attr_done = true;
    }

    // 1. expand circulant weights + round W1/W2 to tf32
    expand_w<<<(NDIM * NDIM + 255) / 256, 256>>>(w_in, w_out);
    round_w<<<(FFD * DD) / 256, 256>>>(W1, W2);

    // 2. LN1: ent -> g_xn (tf32)
    ln_kernel<0><<<ROWS / 8, 256>>>(ent, gamma1, beta1);

    // 3. TT GEMM + residual: g_x = ent + g_xn @ Wbig^T  (4096 x 2048)
    gemm_mma<0><<<dim3(2048 / BN, 4096 / BM), 256, GEMM_SMEM>>>(nullptr, ent, (float*)p_x);

    // 4. LN2: g_x -> g_yn (tf32)
    ln_kernel<1><<<ROWS / 8, 256>>>(nullptr, gamma2, beta2);

    // 5. FFN1: g_hidden = tf32(relu(g_yn @ W1^T + b1))  (32768 x 2048)
    gemm_mma<1><<<dim3(2048 / BN, 32768 / BM), 256, GEMM_SMEM>>>(bias1, nullptr, (float*)p_hid);

    // 6. FFN2: out = g_x + g_hidden @ W2^T + b2  (32768 x 256)
    gemm_mma<2><<<dim3(256 / BN, 32768 / BM), 256, GEMM_SMEM>>>(bias2, (const float*)p_x, out);
}

// round 7
// speedup vs baseline: 2.6001x; 1.0067x over previous
#include <cuda_runtime.h>
#include <cstdint>

// ---------------------------------------------------------------------------
// Problem constants
// ---------------------------------------------------------------------------
#define BB   4096
#define NN   8
#define DD   256
#define FFD  2048
#define NDIM 2048          // N*D
#define ROWS 32768         // B*N

// ---------------------------------------------------------------------------
// Scratch (device globals — no runtime allocation allowed)
// ---------------------------------------------------------------------------
__device__ float g_wt[2u * NDIM * NDIM];        // expanded circulant weights (2 halves stacked: 4096 x 2048)
__device__ float g_xn[(size_t)BB * NDIM];       // LN1 out (tf32-rounded)
__device__ float g_x [(size_t)BB * NDIM];       // post-TT residual (full fp32)
__device__ float g_yn[(size_t)BB * NDIM];       // LN2 out (tf32-rounded)
__device__ float g_hidden[(size_t)ROWS * FFD];  // FFN hidden (tf32-rounded)
__device__ float g_w1r[FFD * DD];               // W1 tf32-rounded
__device__ float g_w2r[DD * FFD];               // W2 tf32-rounded

// ---------------------------------------------------------------------------
// Helpers
// ---------------------------------------------------------------------------
__device__ __forceinline__ float to_tf32(float x) {
    float r;
    asm("cvt.rna.tf32.f32 %0, %1;" : "=f"(r) : "f"(x));
    return r;
}

__device__ __forceinline__ uint32_t smem_u32(const void* p) {
    uint32_t a;
    asm("{ .reg .u64 t; cvta.to.shared.u64 t, %1; cvt.u32.u64 %0, t; }"
        : "=r"(a) : "l"(p));
    return a;
}

#define CP_ASYNC16(dst_u32, src_ptr) \
    asm volatile("cp.async.cg.shared.global [%0], [%1], 16;" \
                 :: "r"(dst_u32), "l"(src_ptr) : "memory")
#define CP_COMMIT() asm volatile("cp.async.commit_group;" ::: "memory")
#define CP_WAIT1()  asm volatile("cp.async.wait_group 1;" ::: "memory")
#define CP_WAIT0()  asm volatile("cp.async.wait_group 0;" ::: "memory")

__device__ __forceinline__ void mma_tf32(float& c0, float& c1, float& c2, float& c3,
                                         uint32_t a0, uint32_t a1, uint32_t a2, uint32_t a3,
                                         uint32_t b0, uint32_t b1) {
    asm volatile(
        "mma.sync.aligned.m16n8k8.row.col.f32.tf32.tf32.f32 "
        "{%0,%1,%2,%3}, {%4,%5,%6,%7}, {%8,%9}, {%0,%1,%2,%3};"
        : "+f"(c0), "+f"(c1), "+f"(c2), "+f"(c3)
        : "r"(a0), "r"(a1), "r"(a2), "r"(a3), "r"(b0), "r"(b1));
}

// ---------------------------------------------------------------------------
// Weight expansion + rounding
// Wt[jcol = kk*D+o][p = i*D+d] = w[d,o,(kk-i)%8]
// ---------------------------------------------------------------------------
__global__ void expand_w(const float* __restrict__ w_in, const float* __restrict__ w_out)
{
    int idx = blockIdx.x * blockDim.x + threadIdx.x;
    if (idx >= NDIM * NDIM) return;
    int j = idx >> 11;
    int p = idx & 2047;
    int kk = j >> 8, o = j & 255;
    int i  = p >> 8, d = p & 255;
    int s  = (kk - i + 8) & 7;
    int widx = (d * DD + o) * NN + s;
    g_wt[idx]               = to_tf32(w_in [widx]);
    g_wt[NDIM * NDIM + idx] = to_tf32(w_out[widx]);
}

__global__ void round_w(const float* __restrict__ W1, const float* __restrict__ W2)
{
    int idx = blockIdx.x * blockDim.x + threadIdx.x;
    g_w1r[idx] = to_tf32(W1[idx]);
    g_w2r[idx] = to_tf32(W2[idx]);
}

// ---------------------------------------------------------------------------
// LayerNorm over D=256, one warp per row; output tf32-rounded
// ---------------------------------------------------------------------------
template<int PH>
__global__ __launch_bounds__(256) void ln_kernel(const float* __restrict__ xin_ext,
                                                 const float* __restrict__ gamma,
                                                 const float* __restrict__ beta)
{
    const float* x   = (PH == 0) ? xin_ext : g_x;
    float*       out = (PH == 0) ? g_xn    : g_yn;

    int warp = threadIdx.x >> 5;
    int lane = threadIdx.x & 31;
    int row  = blockIdx.x * 8 + warp;

    const float* xr = x + (size_t)row * DD;
    float v[8];
    float sum = 0.f;
#pragma unroll
    for (int i = 0; i < 8; i++) { v[i] = xr[lane + 32 * i]; sum += v[i]; }
#pragma unroll
    for (int off = 16; off; off >>= 1) sum += __shfl_xor_sync(0xffffffffu, sum, off);
    float mu = sum * (1.f / 256.f);

    float var = 0.f;
#pragma unroll
    for (int i = 0; i < 8; i++) { float t = v[i] - mu; var += t * t; }
#pragma unroll
    for (int off = 16; off; off >>= 1) var += __shfl_xor_sync(0xffffffffu, var, off);
    float rstd = rsqrtf(var * (1.f / 256.f) + 1e-5f);

    float* orow = out + (size_t)row * DD;
#pragma unroll
    for (int i = 0; i < 8; i++) {
        int c = lane + 32 * i;
        orow[c] = to_tf32((v[i] - mu) * rstd * gamma[c] + beta[c]);
    }
}

// ---------------------------------------------------------------------------
// tf32 mma.sync GEMM: C[m,n] = epi( sum_k A[m,k] * Bt[n,k] )
// BM=128 BN=128 BK=32, 256 threads = 2(M) x 4(N) warps, warp tile 64x32,
// m16n8k8 atoms (4x4 per warp), THREE-stage cp.async pipeline (wait_group 1
// keeps 2 tile loads in flight), one __syncthreads per K-tile, 2 CTAs/SM.
//
// MODE 0: TT (A=g_xn K=2048, Bt=g_wt rows [bn + halfsel*2048], +res(ent) -> g_x)
// MODE 1: FFN1 (A=g_yn K=256, Bt=g_w1r, relu(+bias1), tf32-round -> g_hidden)
// MODE 2: FFN2 (A=g_hidden K=2048, Bt=g_w2r, +bias2 +g_x -> out)
// ---------------------------------------------------------------------------
#define BM 128
#define BN 128
#define BK 32
#define PITCH 36                       // floats per smem row (32 + 4 pad)
#define TILE_FLOATS (128 * PITCH)      // one matrix, one stage
#define STAGE_FLOATS (2 * TILE_FLOATS) // A + B
#define NSTAGE 3
#define GEMM_SMEM (NSTAGE * STAGE_FLOATS * 4)

template<int MODE>
__global__ __launch_bounds__(256, 2) void gemm_mma(
    const float* __restrict__ bias,
    const float* __restrict__ res,
    float* __restrict__ C)
{
    constexpr int K    = (MODE == 1) ? 256 : 2048;
    constexpr int Ncol = (MODE == 2) ? 256 : 2048;
    constexpr int KT   = K / BK;

    const float* A;
    const float* Bt;
    if constexpr (MODE == 0)      { A = g_xn;     Bt = g_wt;  }
    else if constexpr (MODE == 1) { A = g_yn;     Bt = g_w1r; }
    else                          { A = g_hidden; Bt = g_w2r; }

    extern __shared__ float sm[];

    int tid  = threadIdx.x;
    int wid  = tid >> 5;
    int lane = tid & 31;
    int g    = lane >> 2;      // groupID
    int tg   = lane & 3;       // thread-in-group
    int wm   = wid & 1;        // warp M index (0..1)
    int wn   = wid >> 1;       // warp N index (0..3)

    int bm = blockIdx.y * BM;
    int bn = blockIdx.x * BN;
    int brow = bn;
    if (MODE == 0 && bm >= 2048) brow += 2048;   // second-half weight block

    // cp.async assignment: thread t covers row = t>>1, 4 x 16B segs
    int ldrow = tid >> 1;
    int ldseg = (tid & 1) * 4;

    const char* Abase = (const char*)(A  + (size_t)(bm   + ldrow) * K) + ldseg * 16;
    const char* Bbase = (const char*)(Bt + (size_t)(brow + ldrow) * K) + ldseg * 16;
    uint32_t sA = smem_u32(sm) + (uint32_t)(ldrow * PITCH * 4 + ldseg * 16);
    uint32_t sB = sA + TILE_FLOATS * 4;

    auto prefetch = [&](int kt) {
        uint32_t off = (uint32_t)((kt % NSTAGE) * STAGE_FLOATS * 4);
        const char* ag = Abase + (size_t)kt * BK * 4;
        const char* bg = Bbase + (size_t)kt * BK * 4;
#pragma unroll
        for (int s = 0; s < 4; s++) {
            CP_ASYNC16(sA + off + s * 16, ag + s * 16);
            CP_ASYNC16(sB + off + s * 16, bg + s * 16);
        }
    };

    float acc[4][4][4];
#pragma unroll
    for (int mi = 0; mi < 4; mi++)
#pragma unroll
        for (int ni = 0; ni < 4; ni++)
#pragma unroll
            for (int c = 0; c < 4; c++) acc[mi][ni][c] = 0.f;

    // Prime pipeline: tiles 0 and 1 in flight.
    prefetch(0);
    CP_COMMIT();
    if (KT > 1) { prefetch(1); CP_COMMIT(); }

    for (int kt = 0; kt < KT; kt++) {
        // Ensure tile kt's load is done; leave tile kt+1 (if committed) in flight.
        if (kt + 1 < KT) CP_WAIT1(); else CP_WAIT0();
        // Barrier also guarantees everyone finished compute(kt-1), so stage
        // (kt+2)%NSTAGE — the one compute(kt-1) just read — is reusable.
        __syncthreads();

        if (kt + 2 < KT) {
            prefetch(kt + 2);
            CP_COMMIT();
        }

        const float* As = sm + (kt % NSTAGE) * STAGE_FLOATS;
        const float* Bs = As + TILE_FLOATS;
        const uint32_t* Asu = (const uint32_t*)As;
        const uint32_t* Bsu = (const uint32_t*)Bs;

#pragma unroll
        for (int ka = 0; ka < 4; ka++) {
            int kc = ka * 8 + tg;
            uint32_t bf[4][2];
#pragma unroll
            for (int ni = 0; ni < 4; ni++) {
                int n0 = wn * 32 + ni * 8;
                bf[ni][0] = Bsu[(n0 + g) * PITCH + kc];
                bf[ni][1] = Bsu[(n0 + g) * PITCH + kc + 4];
            }
#pragma unroll
            for (int mi = 0; mi < 4; mi++) {
                int m0 = wm * 64 + mi * 16;
                uint32_t a0 = Asu[(m0 + g)     * PITCH + kc];
                uint32_t a1 = Asu[(m0 + g + 8) * PITCH + kc];
                uint32_t a2 = Asu[(m0 + g)     * PITCH + kc + 4];
                uint32_t a3 = Asu[(m0 + g + 8) * PITCH + kc + 4];
#pragma unroll
                for (int ni = 0; ni < 4; ni++)
                    mma_tf32(acc[mi][ni][0], acc[mi][ni][1], acc[mi][ni][2], acc[mi][ni][3],
                             a0, a1, a2, a3, bf[ni][0], bf[ni][1]);
            }
        }
    }

    // ---- epilogue ----
#pragma unroll
    for (int mi = 0; mi < 4; mi++) {
#pragma unroll
        for (int half = 0; half < 2; half++) {
            int row = bm + wm * 64 + mi * 16 + g + half * 8;
#pragma unroll
            for (int ni = 0; ni < 4; ni++) {
                int col = bn + wn * 32 + ni * 8 + tg * 2;
                float v0 = acc[mi][ni][half * 2 + 0];
                float v1 = acc[mi][ni][half * 2 + 1];
                if constexpr (MODE == 0) {
                    const float2 rv = *(const float2*)&res[(size_t)row * 2048 + col];
                    v0 += rv.x; v1 += rv.y;
                } else if constexpr (MODE == 1) {
                    v0 = to_tf32(fmaxf(v0 + bias[col],     0.f));
                    v1 = to_tf32(fmaxf(v1 + bias[col + 1], 0.f));
                } else {
                    const float2 rv = *(const float2*)&res[(size_t)row * 256 + col];
                    v0 += bias[col]     + rv.x;
                    v1 += bias[col + 1] + rv.y;
                }
                float2 o; o.x = v0; o.y = v1;
                *(float2*)&C[(size_t)row * Ncol + col] = o;
            }
        }
    }
}

// ---------------------------------------------------------------------------
// Host side
// ---------------------------------------------------------------------------
extern "C" void kernel_launch(void* const* d_in, const int* in_sizes, int n_in,
                              void* d_out, int out_size)
{
    const float* ent    = (const float*)d_in[0];
    const float* w_in   = (const float*)d_in[1];
    const float* w_out  = (const float*)d_in[2];
    const float* W1     = (const float*)d_in[3];
    const float* bias1  = (const float*)d_in[4];
    const float* W2     = (const float*)d_in[5];
    const float* bias2  = (const float*)d_in[6];
    const float* gamma1 = (const float*)d_in[7];
    const float* beta1  = (const float*)d_in[8];
    const float* gamma2 = (const float*)d_in[9];
    const float* beta2  = (const float*)d_in[10];
    float* out = (float*)d_out;

    void* p_x;
    void* p_hid;
    cudaGetSymbolAddress(&p_x,   g_x);
    cudaGetSymbolAddress(&p_hid, g_hidden);

    static bool attr_done = false;
    if (!attr_done) {
        cudaFuncSetAttribute(gemm_mma<0>, cudaFuncAttributeMaxDynamicSharedMemorySize, GEMM_SMEM);
        cudaFuncSetAttribute(gemm_mma<1>, cudaFuncAttributeMaxDynamicSharedMemorySize, GEMM_SMEM);
        cudaFuncSetAttribute(gemm_mma<2>, cudaFuncAttributeMaxDynamicSharedMemorySize, GEMM_SMEM);
        attr_done = true;
    }

    // 1. expand circulant weights + round W1/W2 to tf32
    expand_w<<<(NDIM * NDIM + 255) / 256, 256>>>(w_in, w_out);
    round_w<<<(FFD * DD) / 256, 256>>>(W1, W2);

    // 2. LN1: ent -> g_xn (tf32)
    ln_kernel<0><<<ROWS / 8, 256>>>(ent, gamma1, beta1);

    // 3. TT GEMM + residual: g_x = ent + g_xn @ Wbig^T  (4096 x 2048)
    gemm_mma<0><<<dim3(2048 / BN, 4096 / BM), 256, GEMM_SMEM>>>(nullptr, ent, (float*)p_x);

    // 4. LN2: g_x -> g_yn (tf32)
    ln_kernel<1><<<ROWS / 8, 256>>>(nullptr, gamma2, beta2);

    // 5. FFN1: g_hidden = tf32(relu(g_yn @ W1^T + b1))  (32768 x 2048)
    gemm_mma<1><<<dim3(2048 / BN, 32768 / BM), 256, GEMM_SMEM>>>(bias1, nullptr, (float*)p_hid);

    // 6. FFN2: out = g_x + g_hidden @ W2^T + b2  (32768 x 256)
    gemm_mma<2><<<dim3(256 / BN, 32768 / BM), 256, GEMM_SMEM>>>(bias2, (const float*)p_x, out);
}

// round 8
// speedup vs baseline: 2.9138x; 1.1206x over previous
#include <cuda_runtime.h>
#include <cstdint>

// ---------------------------------------------------------------------------
// Problem constants
// ---------------------------------------------------------------------------
#define BB   4096
#define NN   8
#define DD   256
#define FFD  2048
#define NDIM 2048          // N*D
#define ROWS 32768         // B*N

// ---------------------------------------------------------------------------
// Scratch (device globals — no runtime allocation allowed)
// ---------------------------------------------------------------------------
__device__ float g_wt[2u * NDIM * NDIM];        // expanded circulant weights (2 halves stacked: 4096 x 2048)
__device__ float g_xn[(size_t)BB * NDIM];       // LN1 out (tf32-rounded)
__device__ float g_x [(size_t)BB * NDIM];       // post-TT residual (full fp32)
__device__ float g_yn[(size_t)BB * NDIM];       // LN2 out (tf32-rounded)
__device__ float g_hidden[(size_t)ROWS * FFD];  // FFN hidden (tf32-rounded)
__device__ float g_w1r[FFD * DD];               // W1 tf32-rounded
__device__ float g_w2r[DD * FFD];               // W2 tf32-rounded

// ---------------------------------------------------------------------------
// Helpers
// ---------------------------------------------------------------------------
__device__ __forceinline__ float to_tf32(float x) {
    float r;
    asm("cvt.rna.tf32.f32 %0, %1;" : "=f"(r) : "f"(x));
    return r;
}

__device__ __forceinline__ uint32_t smem_u32(const void* p) {
    uint32_t a;
    asm("{ .reg .u64 t; cvta.to.shared.u64 t, %1; cvt.u32.u64 %0, t; }"
        : "=r"(a) : "l"(p));
    return a;
}

#define CP_ASYNC16(dst_u32, src_ptr) \
    asm volatile("cp.async.cg.shared.global [%0], [%1], 16;" \
                 :: "r"(dst_u32), "l"(src_ptr) : "memory")
#define CP_COMMIT() asm volatile("cp.async.commit_group;" ::: "memory")
#define CP_WAIT1()  asm volatile("cp.async.wait_group 1;" ::: "memory")
#define CP_WAIT0()  asm volatile("cp.async.wait_group 0;" ::: "memory")

// ldmatrix.x4 on 32-bit (tf32) data: b16 pair packing reconstitutes tf32 words.
#define LDSM_X4(r0, r1, r2, r3, addr) \
    asm volatile("ldmatrix.sync.aligned.m8n8.x4.shared.b16 {%0,%1,%2,%3}, [%4];" \
                 : "=r"(r0), "=r"(r1), "=r"(r2), "=r"(r3) : "r"(addr))

__device__ __forceinline__ void mma_tf32(float& c0, float& c1, float& c2, float& c3,
                                         uint32_t a0, uint32_t a1, uint32_t a2, uint32_t a3,
                                         uint32_t b0, uint32_t b1) {
    asm volatile(
        "mma.sync.aligned.m16n8k8.row.col.f32.tf32.tf32.f32 "
        "{%0,%1,%2,%3}, {%4,%5,%6,%7}, {%8,%9}, {%0,%1,%2,%3};"
        : "+f"(c0), "+f"(c1), "+f"(c2), "+f"(c3)
        : "r"(a0), "r"(a1), "r"(a2), "r"(a3), "r"(b0), "r"(b1));
}

// ---------------------------------------------------------------------------
// Weight expansion + rounding
// Wt[jcol = kk*D+o][p = i*D+d] = w[d,o,(kk-i)%8]
// ---------------------------------------------------------------------------
__global__ void expand_w(const float* __restrict__ w_in, const float* __restrict__ w_out)
{
    int idx = blockIdx.x * blockDim.x + threadIdx.x;
    if (idx >= NDIM * NDIM) return;
    int j = idx >> 11;
    int p = idx & 2047;
    int kk = j >> 8, o = j & 255;
    int i  = p >> 8, d = p & 255;
    int s  = (kk - i + 8) & 7;
    int widx = (d * DD + o) * NN + s;
    g_wt[idx]               = to_tf32(w_in [widx]);
    g_wt[NDIM * NDIM + idx] = to_tf32(w_out[widx]);
}

__global__ void round_w(const float* __restrict__ W1, const float* __restrict__ W2)
{
    int idx = blockIdx.x * blockDim.x + threadIdx.x;
    g_w1r[idx] = to_tf32(W1[idx]);
    g_w2r[idx] = to_tf32(W2[idx]);
}

// ---------------------------------------------------------------------------
// LayerNorm over D=256, one warp per row; output tf32-rounded
// ---------------------------------------------------------------------------
template<int PH>
__global__ __launch_bounds__(256) void ln_kernel(const float* __restrict__ xin_ext,
                                                 const float* __restrict__ gamma,
                                                 const float* __restrict__ beta)
{
    const float* x   = (PH == 0) ? xin_ext : g_x;
    float*       out = (PH == 0) ? g_xn    : g_yn;

    int warp = threadIdx.x >> 5;
    int lane = threadIdx.x & 31;
    int row  = blockIdx.x * 8 + warp;

    const float* xr = x + (size_t)row * DD;
    float v[8];
    float sum = 0.f;
#pragma unroll
    for (int i = 0; i < 8; i++) { v[i] = xr[lane + 32 * i]; sum += v[i]; }
#pragma unroll
    for (int off = 16; off; off >>= 1) sum += __shfl_xor_sync(0xffffffffu, sum, off);
    float mu = sum * (1.f / 256.f);

    float var = 0.f;
#pragma unroll
    for (int i = 0; i < 8; i++) { float t = v[i] - mu; var += t * t; }
#pragma unroll
    for (int off = 16; off; off >>= 1) var += __shfl_xor_sync(0xffffffffu, var, off);
    float rstd = rsqrtf(var * (1.f / 256.f) + 1e-5f);

    float* orow = out + (size_t)row * DD;
#pragma unroll
    for (int i = 0; i < 8; i++) {
        int c = lane + 32 * i;
        orow[c] = to_tf32((v[i] - mu) * rstd * gamma[c] + beta[c]);
    }
}

// ---------------------------------------------------------------------------
// tf32 mma.sync GEMM with ldmatrix fragment loads.
// BM=128 BN=128 BK=32, 256 threads = 2(M) x 4(N) warps, warp tile 64x32,
// m16n8k8 atoms (4x4 per warp), 3-stage cp.async pipeline, 2 CTAs/SM.
//
// MODE 0: TT (A=g_xn K=2048, Bt=g_wt rows [bn + halfsel*2048], +res(ent) -> g_x)
// MODE 1: FFN1 (A=g_yn K=256, Bt=g_w1r, relu(+bias1), tf32-round -> g_hidden)
// MODE 2: FFN2 (A=g_hidden K=2048, Bt=g_w2r, +bias2 +g_x -> out)
// ---------------------------------------------------------------------------
#define BM 128
#define BN 128
#define BK 32
#define PITCH 36                       // floats per smem row (32 + 4 pad); keeps
                                       // LDSM rows 16B-aligned & conflict-free
#define TILE_FLOATS (128 * PITCH)      // one matrix, one stage
#define TILE_BYTES  (TILE_FLOATS * 4)
#define STAGE_FLOATS (2 * TILE_FLOATS) // A + B
#define STAGE_BYTES (STAGE_FLOATS * 4)
#define NSTAGE 3
#define GEMM_SMEM (NSTAGE * STAGE_BYTES)

template<int MODE>
__global__ __launch_bounds__(256, 2) void gemm_mma(
    const float* __restrict__ bias,
    const float* __restrict__ res,
    float* __restrict__ C)
{
    constexpr int K    = (MODE == 1) ? 256 : 2048;
    constexpr int Ncol = (MODE == 2) ? 256 : 2048;
    constexpr int KT   = K / BK;

    const float* A;
    const float* Bt;
    if constexpr (MODE == 0)      { A = g_xn;     Bt = g_wt;  }
    else if constexpr (MODE == 1) { A = g_yn;     Bt = g_w1r; }
    else                          { A = g_hidden; Bt = g_w2r; }

    extern __shared__ float sm[];

    int tid  = threadIdx.x;
    int wid  = tid >> 5;
    int lane = tid & 31;
    int g    = lane >> 2;      // groupID
    int tg   = lane & 3;       // thread-in-group
    int wm   = wid & 1;        // warp M index (0..1)
    int wn   = wid >> 1;       // warp N index (0..3)

    int bm = blockIdx.y * BM;
    int bn = blockIdx.x * BN;
    int brow = bn;
    if (MODE == 0 && bm >= 2048) brow += 2048;   // second-half weight block

    // cp.async assignment: thread t covers row = t>>1, 4 x 16B segs
    int ldrow = tid >> 1;
    int ldseg = (tid & 1) * 4;

    const char* Abase = (const char*)(A  + (size_t)(bm   + ldrow) * K) + ldseg * 16;
    const char* Bbase = (const char*)(Bt + (size_t)(brow + ldrow) * K) + ldseg * 16;
    uint32_t smbase = smem_u32(sm);
    uint32_t sA = smbase + (uint32_t)(ldrow * PITCH * 4 + ldseg * 16);
    uint32_t sB = sA + TILE_BYTES;

    auto prefetch = [&](int kt) {
        uint32_t off = (uint32_t)((kt % NSTAGE) * STAGE_BYTES);
        const char* ag = Abase + (size_t)kt * BK * 4;
        const char* bg = Bbase + (size_t)kt * BK * 4;
#pragma unroll
        for (int s = 0; s < 4; s++) {
            CP_ASYNC16(sA + off + s * 16, ag + s * 16);
            CP_ASYNC16(sB + off + s * 16, bg + s * 16);
        }
    };

    // ldmatrix per-lane row addresses (byte offsets within a stage).
    // A (per mi): matrices [rows m0+g | m0+8+g] x [k | k+4]
    //   lane sel = lane>>3: row += (sel&1)*8, kword += (sel>>1)*4
    // B (per ni2, covering ni=2*ni2, 2*ni2+1):
    //   row += (sel>>1)*8 (ni select), kword += (sel&1)*4 (b0/b1 select)
    int r   = lane & 7;
    int sel = lane >> 3;
    uint32_t aAddr[4], bAddr[2];
#pragma unroll
    for (int mi = 0; mi < 4; mi++)
        aAddr[mi] = smbase +
            4u * ((uint32_t)(wm * 64 + mi * 16 + r + (sel & 1) * 8) * PITCH + (sel >> 1) * 4);
#pragma unroll
    for (int ni2 = 0; ni2 < 2; ni2++)
        bAddr[ni2] = smbase + TILE_BYTES +
            4u * ((uint32_t)(wn * 32 + ni2 * 16 + r + (sel >> 1) * 8) * PITCH + (sel & 1) * 4);

    float acc[4][4][4];
#pragma unroll
    for (int mi = 0; mi < 4; mi++)
#pragma unroll
        for (int ni = 0; ni < 4; ni++)
#pragma unroll
            for (int c = 0; c < 4; c++) acc[mi][ni][c] = 0.f;

    // Prime pipeline: tiles 0 and 1 in flight.
    prefetch(0);
    CP_COMMIT();
    if (KT > 1) { prefetch(1); CP_COMMIT(); }

    for (int kt = 0; kt < KT; kt++) {
        if (kt + 1 < KT) CP_WAIT1(); else CP_WAIT0();
        __syncthreads();

        if (kt + 2 < KT) {
            prefetch(kt + 2);
            CP_COMMIT();
        }

        uint32_t stoff = (uint32_t)((kt % NSTAGE) * STAGE_BYTES);

#pragma unroll
        for (int ka = 0; ka < 4; ka++) {
            uint32_t koff = stoff + ka * 32;   // ka*8 words = 32 bytes
            uint32_t bf[4][2];
            LDSM_X4(bf[0][0], bf[0][1], bf[1][0], bf[1][1], bAddr[0] + koff);
            LDSM_X4(bf[2][0], bf[2][1], bf[3][0], bf[3][1], bAddr[1] + koff);
#pragma unroll
            for (int mi = 0; mi < 4; mi++) {
                uint32_t a0, a1, a2, a3;
                LDSM_X4(a0, a1, a2, a3, aAddr[mi] + koff);
#pragma unroll
                for (int ni = 0; ni < 4; ni++)
                    mma_tf32(acc[mi][ni][0], acc[mi][ni][1], acc[mi][ni][2], acc[mi][ni][3],
                             a0, a1, a2, a3, bf[ni][0], bf[ni][1]);
            }
        }
    }

    // ---- epilogue ----
#pragma unroll
    for (int mi = 0; mi < 4; mi++) {
#pragma unroll
        for (int half = 0; half < 2; half++) {
            int row = bm + wm * 64 + mi * 16 + g + half * 8;
#pragma unroll
            for (int ni = 0; ni < 4; ni++) {
                int col = bn + wn * 32 + ni * 8 + tg * 2;
                float v0 = acc[mi][ni][half * 2 + 0];
                float v1 = acc[mi][ni][half * 2 + 1];
                if constexpr (MODE == 0) {
                    const float2 rv = *(const float2*)&res[(size_t)row * 2048 + col];
                    v0 += rv.x; v1 += rv.y;
                } else if constexpr (MODE == 1) {
                    v0 = to_tf32(fmaxf(v0 + bias[col],     0.f));
                    v1 = to_tf32(fmaxf(v1 + bias[col + 1], 0.f));
                } else {
                    const float2 rv = *(const float2*)&res[(size_t)row * 256 + col];
                    v0 += bias[col]     + rv.x;
                    v1 += bias[col + 1] + rv.y;
                }
                float2 o; o.x = v0; o.y = v1;
                *(float2*)&C[(size_t)row * Ncol + col] = o;
            }
        }
    }
}

// ---------------------------------------------------------------------------
// Host side
// ---------------------------------------------------------------------------
extern "C" void kernel_launch(void* const* d_in, const int* in_sizes, int n_in,
                              void* d_out, int out_size)
{
    const float* ent    = (const float*)d_in[0];
    const float* w_in   = (const float*)d_in[1];
    const float* w_out  = (const float*)d_in[2];
    const float* W1     = (const float*)d_in[3];
    const float* bias1  = (const float*)d_in[4];
    const float* W2     = (const float*)d_in[5];
    const float* bias2  = (const float*)d_in[6];
    const float* gamma1 = (const float*)d_in[7];
    const float* beta1  = (const float*)d_in[8];
    const float* gamma2 = (const float*)d_in[9];
    const float* beta2  = (const float*)d_in[10];
    float* out = (float*)d_out;

    void* p_x;
    void* p_hid;
    cudaGetSymbolAddress(&p_x,   g_x);
    cudaGetSymbolAddress(&p_hid, g_hidden);

    static bool attr_done = false;
    if (!attr_done) {
        cudaFuncSetAttribute(gemm_mma<0>, cudaFuncAttributeMaxDynamicSharedMemorySize, GEMM_SMEM);
        cudaFuncSetAttribute(gemm_mma<1>, cudaFuncAttributeMaxDynamicSharedMemorySize, GEMM_SMEM);
        cudaFuncSetAttribute(gemm_mma<2>, cudaFuncAttributeMaxDynamicSharedMemorySize, GEMM_SMEM);
        attr_done = true;
    }

    // 1. expand circulant weights + round W1/W2 to tf32
    expand_w<<<(NDIM * NDIM + 255) / 256, 256>>>(w_in, w_out);
    round_w<<<(FFD * DD) / 256, 256>>>(W1, W2);

    // 2. LN1: ent -> g_xn (tf32)
    ln_kernel<0><<<ROWS / 8, 256>>>(ent, gamma1, beta1);

    // 3. TT GEMM + residual: g_x = ent + g_xn @ Wbig^T  (4096 x 2048)
    gemm_mma<0><<<dim3(2048 / BN, 4096 / BM), 256, GEMM_SMEM>>>(nullptr, ent, (float*)p_x);

    // 4. LN2: g_x -> g_yn (tf32)
    ln_kernel<1><<<ROWS / 8, 256>>>(nullptr, gamma2, beta2);

    // 5. FFN1: g_hidden = tf32(relu(g_yn @ W1^T + b1))  (32768 x 2048)
    gemm_mma<1><<<dim3(2048 / BN, 32768 / BM), 256, GEMM_SMEM>>>(bias1, nullptr, (float*)p_hid);

    // 6. FFN2: out = g_x + g_hidden @ W2^T + b2  (32768 x 256)
    gemm_mma<2><<<dim3(256 / BN, 32768 / BM), 256, GEMM_SMEM>>>(bias2, (const float*)p_x, out);
}